// round 6
// baseline (speedup 1.0000x reference)
#include <cuda_runtime.h>
#include <cuda_bf16.h>

#define NUM_S 1024
#define EPS_F 1e-6f
#define FIX_SCALE 16777216.0f        // 2^24
#define INV_FIX   (1.0f/16777216.0f)
#define LOW_MASK  0xFFFFFFFFFFFFull  // low 48 bits

// Global scratch (allocation-free rule: __device__ globals).
// Zero-initialized at module load; finalize kernel restores zeros each launch,
// so every kernel_launch call sees the same initial state (graph-safe).
__device__ float g_sse[NUM_S];
__device__ float g_cnt[NUM_S];

__global__ __launch_bounds__(256)
void nse_accum_kernel(const float4* __restrict__ yp,
                      const float4* __restrict__ yt,
                      const int4*  __restrict__ st,
                      int nvec,
                      const float* __restrict__ yp_s,
                      const float* __restrict__ yt_s,
                      const int*   __restrict__ st_s,
                      int rem_start, int n_total)
{
    __shared__ unsigned long long hist[NUM_S];
    for (int i = threadIdx.x; i < NUM_S; i += blockDim.x) hist[i] = 0ull;
    __syncthreads();

    const int tid    = blockIdx.x * blockDim.x + threadIdx.x;
    const int stride = gridDim.x * blockDim.x;

    for (int i = tid; i < nvec; i += stride) {
        float4 p = yp[i];
        float4 t = yt[i];
        int4   s = st[i];
        float d0 = p.x - t.x;
        float d1 = p.y - t.y;
        float d2 = p.z - t.z;
        float d3 = p.w - t.w;
        unsigned long long ONE = 1ull << 48;
        unsigned long long e0 = ONE | (unsigned long long)(fmaf(d0, d0, 0.0f) * FIX_SCALE + 0.5f);
        unsigned long long e1 = ONE | (unsigned long long)(fmaf(d1, d1, 0.0f) * FIX_SCALE + 0.5f);
        unsigned long long e2 = ONE | (unsigned long long)(fmaf(d2, d2, 0.0f) * FIX_SCALE + 0.5f);
        unsigned long long e3 = ONE | (unsigned long long)(fmaf(d3, d3, 0.0f) * FIX_SCALE + 0.5f);
        atomicAdd(&hist[s.x], e0);
        atomicAdd(&hist[s.y], e1);
        atomicAdd(&hist[s.z], e2);
        atomicAdd(&hist[s.w], e3);
    }

    // Scalar tail (N not divisible by 4) — handled by global threads directly.
    for (int i = rem_start + tid; i < n_total; i += stride) {
        float d = yp_s[i] - yt_s[i];
        atomicAdd(&g_sse[st_s[i]], d * d);
        atomicAdd(&g_cnt[st_s[i]], 1.0f);
    }

    __syncthreads();
    for (int i = threadIdx.x; i < NUM_S; i += blockDim.x) {
        unsigned long long v = hist[i];
        if (v) {
            atomicAdd(&g_cnt[i], (float)(unsigned int)(v >> 48));
            atomicAdd(&g_sse[i], (float)(v & LOW_MASK) * INV_FIX);
        }
    }
}

__global__ __launch_bounds__(NUM_S)
void nse_finalize_kernel(const float* __restrict__ station_std,
                         float* __restrict__ out)
{
    __shared__ float red_sum[32];
    __shared__ float red_cnt[32];

    const int i = threadIdx.x;   // exactly NUM_S threads
    float sse = g_sse[i];
    float cnt = g_cnt[i];
    // Restore zeros for the next replay (self-restoring state).
    g_sse[i] = 0.0f;
    g_cnt[i] = 0.0f;

    float sd    = station_std[i] + EPS_F;
    float denom = sd * sd;
    float per   = 0.0f;
    float pres  = 0.0f;
    if (cnt > 0.0f) {
        per  = (sse / cnt) / denom;
        pres = 1.0f;
    }

    #pragma unroll
    for (int o = 16; o > 0; o >>= 1) {
        per  += __shfl_down_sync(0xFFFFFFFFu, per,  o);
        pres += __shfl_down_sync(0xFFFFFFFFu, pres, o);
    }
    if ((threadIdx.x & 31) == 0) {
        red_sum[threadIdx.x >> 5] = per;
        red_cnt[threadIdx.x >> 5] = pres;
    }
    __syncthreads();
    if (threadIdx.x < 32) {
        per  = red_sum[threadIdx.x];
        pres = red_cnt[threadIdx.x];
        #pragma unroll
        for (int o = 16; o > 0; o >>= 1) {
            per  += __shfl_down_sync(0xFFFFFFFFu, per,  o);
            pres += __shfl_down_sync(0xFFFFFFFFu, pres, o);
        }
        if (threadIdx.x == 0) {
            out[0] = per / fmaxf(pres, 1.0f);
        }
    }
}

extern "C" void kernel_launch(void* const* d_in, const int* in_sizes, int n_in,
                              void* d_out, int out_size)
{
    const float* y_pred      = (const float*)d_in[0];
    const float* y_true      = (const float*)d_in[1];
    const int*   stations    = (const int*)d_in[2];
    const float* station_std = (const float*)d_in[3];
    float* out = (float*)d_out;

    const int n    = in_sizes[0];
    const int nvec = n / 4;
    const int rem_start = nvec * 4;

    const int block = 256;
    const int grid  = 1184;   // 8 blocks / SM on 148 SMs

    nse_accum_kernel<<<grid, block>>>(
        (const float4*)y_pred, (const float4*)y_true, (const int4*)stations,
        nvec, y_pred, y_true, stations, rem_start, n);

    nse_finalize_kernel<<<1, NUM_S>>>(station_std, out);
}

// round 7
// speedup vs baseline: 1.4145x; 1.4145x over previous
#include <cuda_runtime.h>
#include <cuda_bf16.h>

#define NUM_S 1024
#define EPS_F 1e-6f
#define SCALE_F   4096.0f            // 2^12 fixed-point for err2
#define INV_SCALE (1.0f/4096.0f)
#define CNT_ONE   (1u << 25)         // count lives in bits [25:32)
#define SSE_MASK  ((1u << 25) - 1)   // sse fixed-point in bits [0:25)

// Global scratch (allocation-free rule: __device__ globals).
// Zero-initialized at load; the last block restores zeros every launch,
// so each kernel_launch/graph replay sees identical initial state.
__device__ float        g_sse[NUM_S];
__device__ float        g_cnt[NUM_S];
__device__ unsigned int g_arrive;

__global__ __launch_bounds__(256, 5)
void nse_fused_kernel(const float4* __restrict__ yp,
                      const float4* __restrict__ yt,
                      const int4*  __restrict__ st,
                      int nvec,
                      const float* __restrict__ yp_s,
                      const float* __restrict__ yt_s,
                      const int*   __restrict__ st_s,
                      int rem_start, int n_total,
                      const float* __restrict__ station_std,
                      float* __restrict__ out)
{
    __shared__ unsigned int hist[NUM_S];
    __shared__ float red_s[8];
    __shared__ float red_c[8];
    __shared__ int   s_is_last;

    #pragma unroll
    for (int i = threadIdx.x; i < NUM_S; i += 256) hist[i] = 0u;
    __syncthreads();

    const int tid    = blockIdx.x * 256 + threadIdx.x;
    const int stride = gridDim.x * 256;

    // ---- main loop: 1-deep software pipeline over vec4 groups ----
    int i = tid;
    if (i < nvec) {
        float4 p = __ldcs(&yp[i]);
        float4 t = __ldcs(&yt[i]);
        int4   s = __ldcs(&st[i]);
        for (int j = i + stride; j < nvec; j += stride) {
            // prefetch next group before touching the atomics
            float4 pn = __ldcs(&yp[j]);
            float4 tn = __ldcs(&yt[j]);
            int4   sn = __ldcs(&st[j]);

            float d0 = p.x - t.x, d1 = p.y - t.y, d2 = p.z - t.z, d3 = p.w - t.w;
            atomicAdd(&hist[s.x], CNT_ONE | (unsigned int)(fmaf(d0, d0, 0.0f) * SCALE_F + 0.5f));
            atomicAdd(&hist[s.y], CNT_ONE | (unsigned int)(fmaf(d1, d1, 0.0f) * SCALE_F + 0.5f));
            atomicAdd(&hist[s.z], CNT_ONE | (unsigned int)(fmaf(d2, d2, 0.0f) * SCALE_F + 0.5f));
            atomicAdd(&hist[s.w], CNT_ONE | (unsigned int)(fmaf(d3, d3, 0.0f) * SCALE_F + 0.5f));

            p = pn; t = tn; s = sn;
        }
        // drain pipeline
        {
            float d0 = p.x - t.x, d1 = p.y - t.y, d2 = p.z - t.z, d3 = p.w - t.w;
            atomicAdd(&hist[s.x], CNT_ONE | (unsigned int)(fmaf(d0, d0, 0.0f) * SCALE_F + 0.5f));
            atomicAdd(&hist[s.y], CNT_ONE | (unsigned int)(fmaf(d1, d1, 0.0f) * SCALE_F + 0.5f));
            atomicAdd(&hist[s.z], CNT_ONE | (unsigned int)(fmaf(d2, d2, 0.0f) * SCALE_F + 0.5f));
            atomicAdd(&hist[s.w], CNT_ONE | (unsigned int)(fmaf(d3, d3, 0.0f) * SCALE_F + 0.5f));
        }
    }

    // ---- scalar tail (N % 4) straight to global accumulators ----
    for (int k = rem_start + tid; k < n_total; k += stride) {
        float d = yp_s[k] - yt_s[k];
        atomicAdd(&g_sse[st_s[k]], d * d);
        atomicAdd(&g_cnt[st_s[k]], 1.0f);
    }

    // ---- flush block histogram to global ----
    __syncthreads();
    #pragma unroll
    for (int k = threadIdx.x; k < NUM_S; k += 256) {
        unsigned int v = hist[k];
        if (v) {
            atomicAdd(&g_cnt[k], (float)(v >> 25));
            atomicAdd(&g_sse[k], (float)(v & SSE_MASK) * INV_SCALE);
        }
    }
    __syncthreads();

    // ---- last-block fused finalize ----
    __threadfence();
    if (threadIdx.x == 0) {
        unsigned int old = atomicAdd(&g_arrive, 1u);
        s_is_last = (old == gridDim.x - 1u) ? 1 : 0;
    }
    __syncthreads();
    if (!s_is_last) return;

    float per = 0.0f, pres = 0.0f;
    #pragma unroll
    for (int k = threadIdx.x; k < NUM_S; k += 256) {
        float sse = g_sse[k];
        float cnt = g_cnt[k];
        g_sse[k] = 0.0f;           // self-restore for next replay
        g_cnt[k] = 0.0f;
        float sd = station_std[k] + EPS_F;
        if (cnt > 0.0f) {
            per  += (sse / cnt) / (sd * sd);
            pres += 1.0f;
        }
    }
    #pragma unroll
    for (int o = 16; o > 0; o >>= 1) {
        per  += __shfl_down_sync(0xFFFFFFFFu, per,  o);
        pres += __shfl_down_sync(0xFFFFFFFFu, pres, o);
    }
    if ((threadIdx.x & 31) == 0) {
        red_s[threadIdx.x >> 5] = per;
        red_c[threadIdx.x >> 5] = pres;
    }
    __syncthreads();
    if (threadIdx.x < 32) {
        per  = (threadIdx.x < 8) ? red_s[threadIdx.x] : 0.0f;
        pres = (threadIdx.x < 8) ? red_c[threadIdx.x] : 0.0f;
        #pragma unroll
        for (int o = 4; o > 0; o >>= 1) {
            per  += __shfl_down_sync(0xFFFFFFFFu, per,  o);
            pres += __shfl_down_sync(0xFFFFFFFFu, pres, o);
        }
        if (threadIdx.x == 0) {
            out[0] = per / fmaxf(pres, 1.0f);
            g_arrive = 0u;          // self-restore for next replay
        }
    }
}

extern "C" void kernel_launch(void* const* d_in, const int* in_sizes, int n_in,
                              void* d_out, int out_size)
{
    const float* y_pred      = (const float*)d_in[0];
    const float* y_true      = (const float*)d_in[1];
    const int*   stations    = (const int*)d_in[2];
    const float* station_std = (const float*)d_in[3];
    float* out = (float*)d_out;

    const int n         = in_sizes[0];
    const int nvec      = n / 4;
    const int rem_start = nvec * 4;

    const int block = 256;
    const int grid  = 740;   // 148 SMs x 5 resident blocks -> exactly one wave

    nse_fused_kernel<<<grid, block>>>(
        (const float4*)y_pred, (const float4*)y_true, (const int4*)stations,
        nvec, y_pred, y_true, stations, rem_start, n,
        station_std, out);
}